// round 4
// baseline (speedup 1.0000x reference)
#include <cuda_runtime.h>
#include <math.h>
#include <stdint.h>

#define D   1024
#define T1  8192
#define T2  4096
#define TT  12288

// GEMM tiling (mma.sync tf32; LDS.128 k-permuted fragment loads)
#define BM 128
#define BN 256
#define BK 32
#define PAD 4
#define ROWF (BK + PAD)                          // 36 floats per SMEM row
#define STAGE_FLOATS ((BM + BN) * ROWF)          // 13824
#define STAGE_BYTES  (STAGE_FLOATS * 4)          // 55296
#define GEMM_SMEM    (2 * STAGE_BYTES)           // 110592 (double buffer)

// -------- scratch (device globals; no allocation anywhere) --------
__device__ float g_xcat[TT * D];
__device__ float g_h[TT * D];
__device__ float g_qkv[TT * 3 * D];
__device__ float g_o[TT * D];
__device__ float g_xa[TT * D];
__device__ float g_u[TT * 4 * D];
// transposed weights [N][K]
__device__ float g_wqkv_t[3 * D * D];
__device__ float g_wo_t[D * D];
__device__ float g_wfc_t[4 * D * D];
__device__ float g_wpr_t[D * 4 * D];

// ---------------- small helpers ----------------
__device__ __forceinline__ uint32_t smem_u32(const void* p) {
    uint32_t a;
    asm("{ .reg .u64 t; cvta.to.shared.u64 t, %1; cvt.u32.u64 %0, t; }"
        : "=r"(a) : "l"(p));
    return a;
}
__device__ __forceinline__ float to_tf32(float x) {
    uint32_t u;
    asm("cvt.rna.tf32.f32 %0, %1;" : "=r"(u) : "f"(x));
    return __uint_as_float(u);
}
__device__ __forceinline__ void cp16(uint32_t s, const void* g) {
    asm volatile("cp.async.cg.shared.global [%0], [%1], 16;" :: "r"(s), "l"(g));
}
__device__ __forceinline__ void cp_commit() {
    asm volatile("cp.async.commit_group;");
}
__device__ __forceinline__ void mma_tf32(float* c, uint32_t a0, uint32_t a1,
                                         uint32_t a2, uint32_t a3,
                                         uint32_t b0, uint32_t b1) {
    asm volatile(
        "mma.sync.aligned.m16n8k8.row.col.f32.tf32.tf32.f32 "
        "{%0,%1,%2,%3}, {%4,%5,%6,%7}, {%8,%9}, {%0,%1,%2,%3};"
        : "+f"(c[0]), "+f"(c[1]), "+f"(c[2]), "+f"(c[3])
        : "r"(a0), "r"(a1), "r"(a2), "r"(a3), "r"(b0), "r"(b1));
}

// ---------------- transpose (W[K][N] -> WT[N][K], tf32-rounded) ----------------
__global__ __launch_bounds__(256) void transpose_kernel(
    const float* __restrict__ in, float* __restrict__ out, int K, int N)
{
    __shared__ float t[32][33];
    int n0 = blockIdx.x * 32, k0 = blockIdx.y * 32;
    int x = threadIdx.x, y = threadIdx.y;   // 32 x 8
    #pragma unroll
    for (int i = 0; i < 32; i += 8)
        t[y + i][x] = in[(size_t)(k0 + y + i) * N + n0 + x];
    __syncthreads();
    #pragma unroll
    for (int i = 0; i < 32; i += 8)
        out[(size_t)(n0 + y + i) * K + k0 + x] = to_tf32(t[x][y + i]);
}

// ---------------- HMMA tf32 GEMM: C = A[MxK] @ BT[NxK]^T (+epilogue) ----------
// EPI: 0 = bias, 1 = bias + QuickGELU (+tf32 round), 2 = bias + residual
// 512 threads: warp grid 4(M) x 4(N), warp tile 32x64.
template<int EPI>
__global__ __launch_bounds__(512, 1) void mma_gemm(
    const float* __restrict__ A, const float* __restrict__ Bt,
    const float* __restrict__ bias, const float* __restrict__ res,
    float* __restrict__ C, int N, int K)
{
    extern __shared__ float sm[];
    const int tid = threadIdx.x, wid = tid >> 5, lane = tid & 31;
    const int m0 = blockIdx.y * BM, n0 = blockIdx.x * BN;
    const int wr = wid & 3, wc = wid >> 2;          // 4 x 4 warps
    const int g = lane >> 2, tq = lane & 3;

    float c[2][8][4];
    #pragma unroll
    for (int mt = 0; mt < 2; mt++)
        #pragma unroll
        for (int nt = 0; nt < 8; nt++)
            #pragma unroll
            for (int j = 0; j < 4; j++) c[mt][nt][j] = 0.f;

    auto load_stage = [&](int s, int kb) {
        float* sA = sm + s * STAGE_FLOATS;
        float* sB = sA + BM * ROWF;
        const float* gA = A  + (size_t)m0 * K + kb * BK;
        const float* gB = Bt + (size_t)n0 * K + kb * BK;
        #pragma unroll
        for (int t = 0; t < 2; t++) {
            int ch = tid + t * 512;
            int r = ch >> 3, kc = ch & 7;
            cp16(smem_u32(sA + r * ROWF + kc * 4), gA + (size_t)r * K + kc * 4);
        }
        #pragma unroll
        for (int t = 0; t < 4; t++) {
            int ch = tid + t * 512;
            int r = ch >> 3, kc = ch & 7;
            cp16(smem_u32(sB + r * ROWF + kc * 4), gB + (size_t)r * K + kc * 4);
        }
    };

    const int iters = K / BK;
    load_stage(0, 0);
    cp_commit();

    for (int i = 0; i < iters; i++) {
        if (i + 1 < iters) {
            load_stage((i + 1) & 1, i + 1);
            cp_commit();
            asm volatile("cp.async.wait_group 1;");
        } else {
            asm volatile("cp.async.wait_group 0;");
        }
        __syncthreads();

        const float* sA = sm + (i & 1) * STAGE_FLOATS;
        const float* sB = sA + BM * ROWF;

        // two k16 chunks; each LDS.128 feeds TWO k8 mma steps via k-permutation:
        // sub-step 0 carries k = 4tq+{0,1}, sub-step 1 carries k = 4tq+{2,3}
        // (identical permutation on A and B keeps the dot product exact).
        #pragma unroll
        for (int kp = 0; kp < 2; kp++) {
            const int kb = kp * 16 + 4 * tq;
            float4 a[2][2];
            #pragma unroll
            for (int mt = 0; mt < 2; mt++) {
                const float* pa = sA + (wr * 32 + mt * 16 + g) * ROWF + kb;
                a[mt][0] = *(const float4*)pa;
                a[mt][1] = *(const float4*)(pa + 8 * ROWF);
            }
            #pragma unroll
            for (int nt = 0; nt < 8; nt++) {
                float4 bv = *(const float4*)(sB + (wc * 64 + nt * 8 + g) * ROWF + kb);
                #pragma unroll
                for (int mt = 0; mt < 2; mt++) {
                    mma_tf32(c[mt][nt],
                             __float_as_uint(a[mt][0].x), __float_as_uint(a[mt][1].x),
                             __float_as_uint(a[mt][0].y), __float_as_uint(a[mt][1].y),
                             __float_as_uint(bv.x), __float_as_uint(bv.y));
                    mma_tf32(c[mt][nt],
                             __float_as_uint(a[mt][0].z), __float_as_uint(a[mt][1].z),
                             __float_as_uint(a[mt][0].w), __float_as_uint(a[mt][1].w),
                             __float_as_uint(bv.z), __float_as_uint(bv.w));
                }
            }
        }
        __syncthreads();
    }

    // epilogue: c0,c1 -> row rb, cols 2tq..2tq+1 ; c2,c3 -> row rb+8
    #pragma unroll
    for (int mt = 0; mt < 2; mt++) {
        size_t rb = (size_t)(m0 + wr * 32 + mt * 16 + g);
        #pragma unroll
        for (int nt = 0; nt < 8; nt++) {
            int col = n0 + wc * 64 + nt * 8 + tq * 2;
            float2 bi = *(const float2*)(bias + col);
            float v0 = c[mt][nt][0] + bi.x;
            float v1 = c[mt][nt][1] + bi.y;
            float v2 = c[mt][nt][2] + bi.x;
            float v3 = c[mt][nt][3] + bi.y;
            if (EPI == 1) {
                v0 = to_tf32(v0 / (1.0f + __expf(-1.702f * v0)));
                v1 = to_tf32(v1 / (1.0f + __expf(-1.702f * v1)));
                v2 = to_tf32(v2 / (1.0f + __expf(-1.702f * v2)));
                v3 = to_tf32(v3 / (1.0f + __expf(-1.702f * v3)));
            }
            if (EPI == 2) {
                float2 r0 = *(const float2*)(res + rb * N + col);
                float2 r1 = *(const float2*)(res + (rb + 8) * N + col);
                v0 += r0.x; v1 += r0.y; v2 += r1.x; v3 += r1.y;
            }
            *(float2*)(C + rb * N + col)       = make_float2(v0, v1);
            *(float2*)(C + (rb + 8) * N + col) = make_float2(v2, v3);
        }
    }
}

// ---------------- LayerNorm (tf32-rounded output) ----------------
__global__ __launch_bounds__(256) void ln_kernel(
    const float* __restrict__ x, const float* __restrict__ g,
    const float* __restrict__ b, float* __restrict__ out)
{
    int t = blockIdx.x;
    const float4* xr = (const float4*)(x + (size_t)t * D);
    float4 v = xr[threadIdx.x];
    float s  = v.x + v.y + v.z + v.w;
    float s2 = v.x*v.x + v.y*v.y + v.z*v.z + v.w*v.w;
    #pragma unroll
    for (int o = 16; o > 0; o >>= 1) {
        s  += __shfl_xor_sync(0xffffffffu, s,  o);
        s2 += __shfl_xor_sync(0xffffffffu, s2, o);
    }
    __shared__ float2 wr[8];
    __shared__ float2 stat;
    int warp = threadIdx.x >> 5, lane = threadIdx.x & 31;
    if (lane == 0) wr[warp] = make_float2(s, s2);
    __syncthreads();
    if (threadIdx.x == 0) {
        float ts = 0.f, ts2 = 0.f;
        #pragma unroll
        for (int i = 0; i < 8; i++) { ts += wr[i].x; ts2 += wr[i].y; }
        float mu  = ts * (1.0f / D);
        float var = ts2 * (1.0f / D) - mu * mu;
        stat = make_float2(mu, rsqrtf(var + 1e-5f));
    }
    __syncthreads();
    float mu = stat.x, rstd = stat.y;
    float4 gv = ((const float4*)g)[threadIdx.x];
    float4 bv = ((const float4*)b)[threadIdx.x];
    float4 o4;
    o4.x = to_tf32((v.x - mu) * rstd * gv.x + bv.x);
    o4.y = to_tf32((v.y - mu) * rstd * gv.y + bv.y);
    o4.z = to_tf32((v.z - mu) * rstd * gv.z + bv.z);
    o4.w = to_tf32((v.w - mu) * rstd * gv.w + bv.w);
    ((float4*)(out + (size_t)t * D))[threadIdx.x] = o4;
}

// ---------------- Flash attention (fp32, 64x64 tiles, DH=64) ----------------
__global__ __launch_bounds__(256) void attn_kernel(
    const float* __restrict__ qkv, float* __restrict__ o, int tok0, int N)
{
    __shared__ float Qt[64 * 64];
    __shared__ float KP[64 * 64];
    __shared__ float Vs[64 * 64];

    int tid = threadIdx.x, tx = tid & 15, ty = tid >> 4;
    int h    = blockIdx.y;
    int base = tok0 + blockIdx.z * N;
    int q0   = blockIdx.x * 64;
    int lr = tid >> 2, lp = (tid & 3) * 16;

    {
        const float* src = qkv + (size_t)(base + q0 + lr) * 3072 + h * 64 + lp;
        #pragma unroll
        for (int i = 0; i < 4; i++) {
            float4 v = *(const float4*)(src + i * 4);
            int d = lp + i * 4;
            Qt[(d + 0) * 64 + lr] = v.x * 0.125f;
            Qt[(d + 1) * 64 + lr] = v.y * 0.125f;
            Qt[(d + 2) * 64 + lr] = v.z * 0.125f;
            Qt[(d + 3) * 64 + lr] = v.w * 0.125f;
        }
    }

    float m[4], l[4], oa[4][4];
    #pragma unroll
    for (int i = 0; i < 4; i++) {
        m[i] = -1e30f; l[i] = 0.f;
        #pragma unroll
        for (int j = 0; j < 4; j++) oa[i][j] = 0.f;
    }

    for (int kt = 0; kt < N; kt += 64) {
        __syncthreads();
        {
            const float* ks = qkv + (size_t)(base + kt + lr) * 3072 + 1024 + h * 64 + lp;
            #pragma unroll
            for (int i = 0; i < 4; i++) {
                float4 kv = *(const float4*)(ks + i * 4);
                int d = lp + i * 4;
                KP[(d + 0) * 64 + lr] = kv.x;
                KP[(d + 1) * 64 + lr] = kv.y;
                KP[(d + 2) * 64 + lr] = kv.z;
                KP[(d + 3) * 64 + lr] = kv.w;
            }
            const float* vsp = ks + 1024;
            #pragma unroll
            for (int i = 0; i < 4; i++)
                *(float4*)&Vs[lr * 64 + lp + i * 4] = *(const float4*)(vsp + i * 4);
        }
        __syncthreads();

        float s[4][4];
        #pragma unroll
        for (int i = 0; i < 4; i++)
            #pragma unroll
            for (int j = 0; j < 4; j++) s[i][j] = 0.f;
        #pragma unroll 8
        for (int d = 0; d < 64; d++) {
            float4 a = *(const float4*)&Qt[d * 64 + ty * 4];
            float4 b = *(const float4*)&KP[d * 64 + tx * 4];
            s[0][0] = fmaf(a.x, b.x, s[0][0]); s[0][1] = fmaf(a.x, b.y, s[0][1]);
            s[0][2] = fmaf(a.x, b.z, s[0][2]); s[0][3] = fmaf(a.x, b.w, s[0][3]);
            s[1][0] = fmaf(a.y, b.x, s[1][0]); s[1][1] = fmaf(a.y, b.y, s[1][1]);
            s[1][2] = fmaf(a.y, b.z, s[1][2]); s[1][3] = fmaf(a.y, b.w, s[1][3]);
            s[2][0] = fmaf(a.z, b.x, s[2][0]); s[2][1] = fmaf(a.z, b.y, s[2][1]);
            s[2][2] = fmaf(a.z, b.z, s[2][2]); s[2][3] = fmaf(a.z, b.w, s[2][3]);
            s[3][0] = fmaf(a.w, b.x, s[3][0]); s[3][1] = fmaf(a.w, b.y, s[3][1]);
            s[3][2] = fmaf(a.w, b.z, s[3][2]); s[3][3] = fmaf(a.w, b.w, s[3][3]);
        }

        #pragma unroll
        for (int i = 0; i < 4; i++) {
            float tmax = fmaxf(fmaxf(s[i][0], s[i][1]), fmaxf(s[i][2], s[i][3]));
            #pragma unroll
            for (int off = 8; off > 0; off >>= 1)
                tmax = fmaxf(tmax, __shfl_xor_sync(0xffffffffu, tmax, off));
            float mn = fmaxf(m[i], tmax);
            float al = __expf(m[i] - mn);
            m[i] = mn;
            float rs = 0.f;
            #pragma unroll
            for (int j = 0; j < 4; j++) { s[i][j] = __expf(s[i][j] - mn); rs += s[i][j]; }
            #pragma unroll
            for (int off = 8; off > 0; off >>= 1)
                rs += __shfl_xor_sync(0xffffffffu, rs, off);
            l[i] = l[i] * al + rs;
            #pragma unroll
            for (int j = 0; j < 4; j++) oa[i][j] *= al;
        }

        __syncthreads();
        #pragma unroll
        for (int i = 0; i < 4; i++)
            *(float4*)&KP[(ty * 4 + i) * 64 + tx * 4] =
                make_float4(s[i][0], s[i][1], s[i][2], s[i][3]);
        __syncthreads();

        #pragma unroll 4
        for (int k = 0; k < 64; k++) {
            float4 v = *(const float4*)&Vs[k * 64 + tx * 4];
            #pragma unroll
            for (int i = 0; i < 4; i++) {
                float p = KP[(ty * 4 + i) * 64 + k];
                oa[i][0] = fmaf(p, v.x, oa[i][0]);
                oa[i][1] = fmaf(p, v.y, oa[i][1]);
                oa[i][2] = fmaf(p, v.z, oa[i][2]);
                oa[i][3] = fmaf(p, v.w, oa[i][3]);
            }
        }
    }

    #pragma unroll
    for (int i = 0; i < 4; i++) {
        float inv = 1.0f / l[i];
        int row = base + q0 + ty * 4 + i;
        float4 v = make_float4(to_tf32(oa[i][0] * inv), to_tf32(oa[i][1] * inv),
                               to_tf32(oa[i][2] * inv), to_tf32(oa[i][3] * inv));
        *(float4*)(o + (size_t)row * 1024 + h * 64 + tx * 4) = v;
    }
}

// ---------------- launch ----------------
extern "C" void kernel_launch(void* const* d_in, const int* in_sizes, int n_in,
                              void* d_out, int out_size)
{
    const float* x1    = (const float*)d_in[0];
    const float* x2    = (const float*)d_in[1];
    const float* w_qkv = (const float*)d_in[2];
    const float* b_qkv = (const float*)d_in[3];
    const float* w_o   = (const float*)d_in[4];
    const float* b_o   = (const float*)d_in[5];
    const float* g1    = (const float*)d_in[6];
    const float* be1   = (const float*)d_in[7];
    const float* w_fc  = (const float*)d_in[8];
    const float* b_fc  = (const float*)d_in[9];
    const float* w_pr  = (const float*)d_in[10];
    const float* b_pr  = (const float*)d_in[11];
    const float* g2    = (const float*)d_in[12];
    const float* be2   = (const float*)d_in[13];
    float* out = (float*)d_out;

    float *xcat, *h, *qkvb, *ob, *xa, *ub;
    float *wqkv_t, *wo_t, *wfc_t, *wpr_t;
    cudaGetSymbolAddress((void**)&xcat,   g_xcat);
    cudaGetSymbolAddress((void**)&h,      g_h);
    cudaGetSymbolAddress((void**)&qkvb,   g_qkv);
    cudaGetSymbolAddress((void**)&ob,     g_o);
    cudaGetSymbolAddress((void**)&xa,     g_xa);
    cudaGetSymbolAddress((void**)&ub,     g_u);
    cudaGetSymbolAddress((void**)&wqkv_t, g_wqkv_t);
    cudaGetSymbolAddress((void**)&wo_t,   g_wo_t);
    cudaGetSymbolAddress((void**)&wfc_t,  g_wfc_t);
    cudaGetSymbolAddress((void**)&wpr_t,  g_wpr_t);

    cudaFuncSetAttribute(mma_gemm<0>, cudaFuncAttributeMaxDynamicSharedMemorySize, GEMM_SMEM);
    cudaFuncSetAttribute(mma_gemm<1>, cudaFuncAttributeMaxDynamicSharedMemorySize, GEMM_SMEM);
    cudaFuncSetAttribute(mma_gemm<2>, cudaFuncAttributeMaxDynamicSharedMemorySize, GEMM_SMEM);

    // concat tokens
    cudaMemcpyAsync(xcat, x1, (size_t)T1 * D * sizeof(float),
                    cudaMemcpyDeviceToDevice, 0);
    cudaMemcpyAsync(xcat + (size_t)T1 * D, x2, (size_t)T2 * D * sizeof(float),
                    cudaMemcpyDeviceToDevice, 0);

    // weight transposes (tf32-rounded)
    transpose_kernel<<<dim3(3072 / 32, 1024 / 32), dim3(32, 8)>>>(w_qkv, wqkv_t, 1024, 3072);
    transpose_kernel<<<dim3(1024 / 32, 1024 / 32), dim3(32, 8)>>>(w_o,   wo_t,   1024, 1024);
    transpose_kernel<<<dim3(4096 / 32, 1024 / 32), dim3(32, 8)>>>(w_fc,  wfc_t,  1024, 4096);
    transpose_kernel<<<dim3(1024 / 32, 4096 / 32), dim3(32, 8)>>>(w_pr,  wpr_t,  4096, 1024);

    // LN1
    ln_kernel<<<TT, 256>>>(xcat, g1, be1, h);
    // QKV projection
    mma_gemm<0><<<dim3(3072 / BN, TT / BM), 512, GEMM_SMEM>>>(
        h, wqkv_t, b_qkv, nullptr, qkvb, 3072, 1024);
    // attention
    attn_kernel<<<dim3(16, 16, 8),  256>>>(qkvb, ob, 0,  1024);
    attn_kernel<<<dim3(4,  16, 16), 256>>>(qkvb, ob, T1, 256);
    // out projection + residual
    mma_gemm<2><<<dim3(1024 / BN, TT / BM), 512, GEMM_SMEM>>>(
        ob, wo_t, b_o, xcat, xa, 1024, 1024);
    // LN2
    ln_kernel<<<TT, 256>>>(xa, g2, be2, h);
    // FC + QuickGELU
    mma_gemm<1><<<dim3(4096 / BN, TT / BM), 512, GEMM_SMEM>>>(
        h, wfc_t, b_fc, nullptr, ub, 4096, 1024);
    // projection + residual -> output
    mma_gemm<2><<<dim3(1024 / BN, TT / BM), 512, GEMM_SMEM>>>(
        ub, wpr_t, b_pr, xa, out, 1024, 4096);
}

// round 5
// speedup vs baseline: 1.2505x; 1.2505x over previous
#include <cuda_runtime.h>
#include <math.h>
#include <stdint.h>

#define D   1024
#define T1  8192
#define T2  4096
#define TT  12288

// GEMM tiling (mma.sync tf32; LDS.64 k-permuted fragment loads, conflict-free)
#define BM 128
#define BN 128
#define BK 32
#define PAD 8
#define ROWF (BK + PAD)                          // 40 floats per SMEM row
#define STAGE_FLOATS ((BM + BN) * ROWF)          // 10240
#define STAGE_BYTES  (STAGE_FLOATS * 4)          // 40960
#define GEMM_SMEM    (2 * STAGE_BYTES)           // 81920 (double buffer, 2 CTA/SM)

// -------- scratch (device globals; no allocation anywhere) --------
__device__ float g_xcat[TT * D];
__device__ float g_h[TT * D];
__device__ float g_qkv[TT * 3 * D];
__device__ float g_o[TT * D];
__device__ float g_xa[TT * D];
__device__ float g_u[TT * 4 * D];
// transposed weights [N][K]
__device__ float g_wqkv_t[3 * D * D];
__device__ float g_wo_t[D * D];
__device__ float g_wfc_t[4 * D * D];
__device__ float g_wpr_t[D * 4 * D];

// ---------------- small helpers ----------------
__device__ __forceinline__ uint32_t smem_u32(const void* p) {
    uint32_t a;
    asm("{ .reg .u64 t; cvta.to.shared.u64 t, %1; cvt.u32.u64 %0, t; }"
        : "=r"(a) : "l"(p));
    return a;
}
__device__ __forceinline__ float to_tf32(float x) {
    uint32_t u;
    asm("cvt.rna.tf32.f32 %0, %1;" : "=r"(u) : "f"(x));
    return __uint_as_float(u);
}
__device__ __forceinline__ void cp16(uint32_t s, const void* g) {
    asm volatile("cp.async.cg.shared.global [%0], [%1], 16;" :: "r"(s), "l"(g));
}
__device__ __forceinline__ void cp_commit() {
    asm volatile("cp.async.commit_group;");
}
__device__ __forceinline__ void mma_tf32(float* c, uint32_t a0, uint32_t a1,
                                         uint32_t a2, uint32_t a3,
                                         uint32_t b0, uint32_t b1) {
    asm volatile(
        "mma.sync.aligned.m16n8k8.row.col.f32.tf32.tf32.f32 "
        "{%0,%1,%2,%3}, {%4,%5,%6,%7}, {%8,%9}, {%0,%1,%2,%3};"
        : "+f"(c[0]), "+f"(c[1]), "+f"(c[2]), "+f"(c[3])
        : "r"(a0), "r"(a1), "r"(a2), "r"(a3), "r"(b0), "r"(b1));
}

// ---------------- transpose (W[K][N] -> WT[N][K], tf32-rounded) ----------------
__global__ __launch_bounds__(256) void transpose_kernel(
    const float* __restrict__ in, float* __restrict__ out, int K, int N)
{
    __shared__ float t[32][33];
    int n0 = blockIdx.x * 32, k0 = blockIdx.y * 32;
    int x = threadIdx.x, y = threadIdx.y;   // 32 x 8
    #pragma unroll
    for (int i = 0; i < 32; i += 8)
        t[y + i][x] = in[(size_t)(k0 + y + i) * N + n0 + x];
    __syncthreads();
    #pragma unroll
    for (int i = 0; i < 32; i += 8)
        out[(size_t)(n0 + y + i) * K + k0 + x] = to_tf32(t[x][y + i]);
}

// ---------------- HMMA tf32 GEMM: C = A[MxK] @ BT[NxK]^T (+epilogue) ----------
// EPI: 0 = bias, 1 = bias + QuickGELU (+tf32 round), 2 = bias + residual
// 256 threads: warp grid 4(M) x 2(N), warp tile 32x64.
// k-slot permutation: MMA slot pair (tq, tq+4) carries physical k = (2tq, 2tq+1),
// identical on A and B, so each fragment pair is ONE conflict-free LDS.64.
template<int EPI>
__global__ __launch_bounds__(256, 2) void mma_gemm(
    const float* __restrict__ A, const float* __restrict__ Bt,
    const float* __restrict__ bias, const float* __restrict__ res,
    float* __restrict__ C, int N, int K)
{
    extern __shared__ float sm[];
    const int tid = threadIdx.x, wid = tid >> 5, lane = tid & 31;
    const int m0 = blockIdx.y * BM, n0 = blockIdx.x * BN;
    const int wr = wid & 3, wc = wid >> 2;          // warp grid 4 (M) x 2 (N)
    const int g = lane >> 2, tq = lane & 3;

    float c[2][8][4];
    #pragma unroll
    for (int mt = 0; mt < 2; mt++)
        #pragma unroll
        for (int nt = 0; nt < 8; nt++)
            #pragma unroll
            for (int j = 0; j < 4; j++) c[mt][nt][j] = 0.f;

    auto load_stage = [&](int s, int kb) {
        float* sA = sm + s * STAGE_FLOATS;
        float* sB = sA + BM * ROWF;
        const float* gA = A  + (size_t)m0 * K + kb * BK;
        const float* gB = Bt + (size_t)n0 * K + kb * BK;
        #pragma unroll
        for (int t = 0; t < 4; t++) {
            int ch = tid + t * 256;
            int r = ch >> 3, kc = ch & 7;
            cp16(smem_u32(sA + r * ROWF + kc * 4), gA + (size_t)r * K + kc * 4);
        }
        #pragma unroll
        for (int t = 0; t < 4; t++) {
            int ch = tid + t * 256;
            int r = ch >> 3, kc = ch & 7;
            cp16(smem_u32(sB + r * ROWF + kc * 4), gB + (size_t)r * K + kc * 4);
        }
    };

    const int iters = K / BK;
    load_stage(0, 0);
    cp_commit();

    for (int i = 0; i < iters; i++) {
        if (i + 1 < iters) {
            load_stage((i + 1) & 1, i + 1);
            cp_commit();
            asm volatile("cp.async.wait_group 1;");
        } else {
            asm volatile("cp.async.wait_group 0;");
        }
        __syncthreads();

        const float* sA = sm + (i & 1) * STAGE_FLOATS;
        const float* sB = sA + BM * ROWF;

        #pragma unroll
        for (int k0 = 0; k0 < BK; k0 += 8) {
            const int kb = k0 + 2 * tq;
            float2 a_lo[2], a_hi[2];
            #pragma unroll
            for (int mt = 0; mt < 2; mt++) {
                const float* pa = sA + (wr * 32 + mt * 16 + g) * ROWF + kb;
                a_lo[mt] = *(const float2*)pa;
                a_hi[mt] = *(const float2*)(pa + 8 * ROWF);
            }
            #pragma unroll
            for (int nt = 0; nt < 8; nt++) {
                float2 bv = *(const float2*)(sB + (wc * 64 + nt * 8 + g) * ROWF + kb);
                #pragma unroll
                for (int mt = 0; mt < 2; mt++)
                    mma_tf32(c[mt][nt],
                             __float_as_uint(a_lo[mt].x), __float_as_uint(a_hi[mt].x),
                             __float_as_uint(a_lo[mt].y), __float_as_uint(a_hi[mt].y),
                             __float_as_uint(bv.x), __float_as_uint(bv.y));
            }
        }
        __syncthreads();
    }

    // epilogue: c0,c1 -> row rb, cols 2tq..2tq+1 ; c2,c3 -> row rb+8
    #pragma unroll
    for (int mt = 0; mt < 2; mt++) {
        size_t rb = (size_t)(m0 + wr * 32 + mt * 16 + g);
        #pragma unroll
        for (int nt = 0; nt < 8; nt++) {
            int col = n0 + wc * 64 + nt * 8 + tq * 2;
            float2 bi = *(const float2*)(bias + col);
            float v0 = c[mt][nt][0] + bi.x;
            float v1 = c[mt][nt][1] + bi.y;
            float v2 = c[mt][nt][2] + bi.x;
            float v3 = c[mt][nt][3] + bi.y;
            if (EPI == 1) {
                v0 = to_tf32(v0 / (1.0f + __expf(-1.702f * v0)));
                v1 = to_tf32(v1 / (1.0f + __expf(-1.702f * v1)));
                v2 = to_tf32(v2 / (1.0f + __expf(-1.702f * v2)));
                v3 = to_tf32(v3 / (1.0f + __expf(-1.702f * v3)));
            }
            if (EPI == 2) {
                float2 r0 = *(const float2*)(res + rb * N + col);
                float2 r1 = *(const float2*)(res + (rb + 8) * N + col);
                v0 += r0.x; v1 += r0.y; v2 += r1.x; v3 += r1.y;
            }
            *(float2*)(C + rb * N + col)       = make_float2(v0, v1);
            *(float2*)(C + (rb + 8) * N + col) = make_float2(v2, v3);
        }
    }
}

// ---------------- LayerNorm (tf32-rounded output) ----------------
__global__ __launch_bounds__(256) void ln_kernel(
    const float* __restrict__ x, const float* __restrict__ g,
    const float* __restrict__ b, float* __restrict__ out)
{
    int t = blockIdx.x;
    const float4* xr = (const float4*)(x + (size_t)t * D);
    float4 v = xr[threadIdx.x];
    float s  = v.x + v.y + v.z + v.w;
    float s2 = v.x*v.x + v.y*v.y + v.z*v.z + v.w*v.w;
    #pragma unroll
    for (int o = 16; o > 0; o >>= 1) {
        s  += __shfl_xor_sync(0xffffffffu, s,  o);
        s2 += __shfl_xor_sync(0xffffffffu, s2, o);
    }
    __shared__ float2 wr[8];
    __shared__ float2 stat;
    int warp = threadIdx.x >> 5, lane = threadIdx.x & 31;
    if (lane == 0) wr[warp] = make_float2(s, s2);
    __syncthreads();
    if (threadIdx.x == 0) {
        float ts = 0.f, ts2 = 0.f;
        #pragma unroll
        for (int i = 0; i < 8; i++) { ts += wr[i].x; ts2 += wr[i].y; }
        float mu  = ts * (1.0f / D);
        float var = ts2 * (1.0f / D) - mu * mu;
        stat = make_float2(mu, rsqrtf(var + 1e-5f));
    }
    __syncthreads();
    float mu = stat.x, rstd = stat.y;
    float4 gv = ((const float4*)g)[threadIdx.x];
    float4 bv = ((const float4*)b)[threadIdx.x];
    float4 o4;
    o4.x = to_tf32((v.x - mu) * rstd * gv.x + bv.x);
    o4.y = to_tf32((v.y - mu) * rstd * gv.y + bv.y);
    o4.z = to_tf32((v.z - mu) * rstd * gv.z + bv.z);
    o4.w = to_tf32((v.w - mu) * rstd * gv.w + bv.w);
    ((float4*)(out + (size_t)t * D))[threadIdx.x] = o4;
}

// ---------------- Flash attention (fp32, 64x64 tiles, DH=64) ----------------
__global__ __launch_bounds__(256) void attn_kernel(
    const float* __restrict__ qkv, float* __restrict__ o, int tok0, int N)
{
    __shared__ float Qt[64 * 64];
    __shared__ float KP[64 * 64];
    __shared__ float Vs[64 * 64];

    int tid = threadIdx.x, tx = tid & 15, ty = tid >> 4;
    int h    = blockIdx.y;
    int base = tok0 + blockIdx.z * N;
    int q0   = blockIdx.x * 64;
    int lr = tid >> 2, lp = (tid & 3) * 16;

    {
        const float* src = qkv + (size_t)(base + q0 + lr) * 3072 + h * 64 + lp;
        #pragma unroll
        for (int i = 0; i < 4; i++) {
            float4 v = *(const float4*)(src + i * 4);
            int d = lp + i * 4;
            Qt[(d + 0) * 64 + lr] = v.x * 0.125f;
            Qt[(d + 1) * 64 + lr] = v.y * 0.125f;
            Qt[(d + 2) * 64 + lr] = v.z * 0.125f;
            Qt[(d + 3) * 64 + lr] = v.w * 0.125f;
        }
    }

    float m[4], l[4], oa[4][4];
    #pragma unroll
    for (int i = 0; i < 4; i++) {
        m[i] = -1e30f; l[i] = 0.f;
        #pragma unroll
        for (int j = 0; j < 4; j++) oa[i][j] = 0.f;
    }

    for (int kt = 0; kt < N; kt += 64) {
        __syncthreads();
        {
            const float* ks = qkv + (size_t)(base + kt + lr) * 3072 + 1024 + h * 64 + lp;
            #pragma unroll
            for (int i = 0; i < 4; i++) {
                float4 kv = *(const float4*)(ks + i * 4);
                int d = lp + i * 4;
                KP[(d + 0) * 64 + lr] = kv.x;
                KP[(d + 1) * 64 + lr] = kv.y;
                KP[(d + 2) * 64 + lr] = kv.z;
                KP[(d + 3) * 64 + lr] = kv.w;
            }
            const float* vsp = ks + 1024;
            #pragma unroll
            for (int i = 0; i < 4; i++)
                *(float4*)&Vs[lr * 64 + lp + i * 4] = *(const float4*)(vsp + i * 4);
        }
        __syncthreads();

        float s[4][4];
        #pragma unroll
        for (int i = 0; i < 4; i++)
            #pragma unroll
            for (int j = 0; j < 4; j++) s[i][j] = 0.f;
        #pragma unroll 8
        for (int d = 0; d < 64; d++) {
            float4 a = *(const float4*)&Qt[d * 64 + ty * 4];
            float4 b = *(const float4*)&KP[d * 64 + tx * 4];
            s[0][0] = fmaf(a.x, b.x, s[0][0]); s[0][1] = fmaf(a.x, b.y, s[0][1]);
            s[0][2] = fmaf(a.x, b.z, s[0][2]); s[0][3] = fmaf(a.x, b.w, s[0][3]);
            s[1][0] = fmaf(a.y, b.x, s[1][0]); s[1][1] = fmaf(a.y, b.y, s[1][1]);
            s[1][2] = fmaf(a.y, b.z, s[1][2]); s[1][3] = fmaf(a.y, b.w, s[1][3]);
            s[2][0] = fmaf(a.z, b.x, s[2][0]); s[2][1] = fmaf(a.z, b.y, s[2][1]);
            s[2][2] = fmaf(a.z, b.z, s[2][2]); s[2][3] = fmaf(a.z, b.w, s[2][3]);
            s[3][0] = fmaf(a.w, b.x, s[3][0]); s[3][1] = fmaf(a.w, b.y, s[3][1]);
            s[3][2] = fmaf(a.w, b.z, s[3][2]); s[3][3] = fmaf(a.w, b.w, s[3][3]);
        }

        #pragma unroll
        for (int i = 0; i < 4; i++) {
            float tmax = fmaxf(fmaxf(s[i][0], s[i][1]), fmaxf(s[i][2], s[i][3]));
            #pragma unroll
            for (int off = 8; off > 0; off >>= 1)
                tmax = fmaxf(tmax, __shfl_xor_sync(0xffffffffu, tmax, off));
            float mn = fmaxf(m[i], tmax);
            float al = __expf(m[i] - mn);
            m[i] = mn;
            float rs = 0.f;
            #pragma unroll
            for (int j = 0; j < 4; j++) { s[i][j] = __expf(s[i][j] - mn); rs += s[i][j]; }
            #pragma unroll
            for (int off = 8; off > 0; off >>= 1)
                rs += __shfl_xor_sync(0xffffffffu, rs, off);
            l[i] = l[i] * al + rs;
            #pragma unroll
            for (int j = 0; j < 4; j++) oa[i][j] *= al;
        }

        __syncthreads();
        #pragma unroll
        for (int i = 0; i < 4; i++)
            *(float4*)&KP[(ty * 4 + i) * 64 + tx * 4] =
                make_float4(s[i][0], s[i][1], s[i][2], s[i][3]);
        __syncthreads();

        #pragma unroll 4
        for (int k = 0; k < 64; k++) {
            float4 v = *(const float4*)&Vs[k * 64 + tx * 4];
            #pragma unroll
            for (int i = 0; i < 4; i++) {
                float p = KP[(ty * 4 + i) * 64 + k];
                oa[i][0] = fmaf(p, v.x, oa[i][0]);
                oa[i][1] = fmaf(p, v.y, oa[i][1]);
                oa[i][2] = fmaf(p, v.z, oa[i][2]);
                oa[i][3] = fmaf(p, v.w, oa[i][3]);
            }
        }
    }

    #pragma unroll
    for (int i = 0; i < 4; i++) {
        float inv = 1.0f / l[i];
        int row = base + q0 + ty * 4 + i;
        float4 v = make_float4(to_tf32(oa[i][0] * inv), to_tf32(oa[i][1] * inv),
                               to_tf32(oa[i][2] * inv), to_tf32(oa[i][3] * inv));
        *(float4*)(o + (size_t)row * 1024 + h * 64 + tx * 4) = v;
    }
}

// ---------------- launch ----------------
extern "C" void kernel_launch(void* const* d_in, const int* in_sizes, int n_in,
                              void* d_out, int out_size)
{
    const float* x1    = (const float*)d_in[0];
    const float* x2    = (const float*)d_in[1];
    const float* w_qkv = (const float*)d_in[2];
    const float* b_qkv = (const float*)d_in[3];
    const float* w_o   = (const float*)d_in[4];
    const float* b_o   = (const float*)d_in[5];
    const float* g1    = (const float*)d_in[6];
    const float* be1   = (const float*)d_in[7];
    const float* w_fc  = (const float*)d_in[8];
    const float* b_fc  = (const float*)d_in[9];
    const float* w_pr  = (const float*)d_in[10];
    const float* b_pr  = (const float*)d_in[11];
    const float* g2    = (const float*)d_in[12];
    const float* be2   = (const float*)d_in[13];
    float* out = (float*)d_out;

    float *xcat, *h, *qkvb, *ob, *xa, *ub;
    float *wqkv_t, *wo_t, *wfc_t, *wpr_t;
    cudaGetSymbolAddress((void**)&xcat,   g_xcat);
    cudaGetSymbolAddress((void**)&h,      g_h);
    cudaGetSymbolAddress((void**)&qkvb,   g_qkv);
    cudaGetSymbolAddress((void**)&ob,     g_o);
    cudaGetSymbolAddress((void**)&xa,     g_xa);
    cudaGetSymbolAddress((void**)&ub,     g_u);
    cudaGetSymbolAddress((void**)&wqkv_t, g_wqkv_t);
    cudaGetSymbolAddress((void**)&wo_t,   g_wo_t);
    cudaGetSymbolAddress((void**)&wfc_t,  g_wfc_t);
    cudaGetSymbolAddress((void**)&wpr_t,  g_wpr_t);

    cudaFuncSetAttribute(mma_gemm<0>, cudaFuncAttributeMaxDynamicSharedMemorySize, GEMM_SMEM);
    cudaFuncSetAttribute(mma_gemm<1>, cudaFuncAttributeMaxDynamicSharedMemorySize, GEMM_SMEM);
    cudaFuncSetAttribute(mma_gemm<2>, cudaFuncAttributeMaxDynamicSharedMemorySize, GEMM_SMEM);

    // concat tokens
    cudaMemcpyAsync(xcat, x1, (size_t)T1 * D * sizeof(float),
                    cudaMemcpyDeviceToDevice, 0);
    cudaMemcpyAsync(xcat + (size_t)T1 * D, x2, (size_t)T2 * D * sizeof(float),
                    cudaMemcpyDeviceToDevice, 0);

    // weight transposes (tf32-rounded)
    transpose_kernel<<<dim3(3072 / 32, 1024 / 32), dim3(32, 8)>>>(w_qkv, wqkv_t, 1024, 3072);
    transpose_kernel<<<dim3(1024 / 32, 1024 / 32), dim3(32, 8)>>>(w_o,   wo_t,   1024, 1024);
    transpose_kernel<<<dim3(4096 / 32, 1024 / 32), dim3(32, 8)>>>(w_fc,  wfc_t,  1024, 4096);
    transpose_kernel<<<dim3(1024 / 32, 4096 / 32), dim3(32, 8)>>>(w_pr,  wpr_t,  4096, 1024);

    // LN1
    ln_kernel<<<TT, 256>>>(xcat, g1, be1, h);
    // QKV projection
    mma_gemm<0><<<dim3(3072 / BN, TT / BM), 256, GEMM_SMEM>>>(
        h, wqkv_t, b_qkv, nullptr, qkvb, 3072, 1024);
    // attention
    attn_kernel<<<dim3(16, 16, 8),  256>>>(qkvb, ob, 0,  1024);
    attn_kernel<<<dim3(4,  16, 16), 256>>>(qkvb, ob, T1, 256);
    // out projection + residual
    mma_gemm<2><<<dim3(1024 / BN, TT / BM), 256, GEMM_SMEM>>>(
        ob, wo_t, b_o, xcat, xa, 1024, 1024);
    // LN2
    ln_kernel<<<TT, 256>>>(xa, g2, be2, h);
    // FC + QuickGELU
    mma_gemm<1><<<dim3(4096 / BN, TT / BM), 256, GEMM_SMEM>>>(
        h, wfc_t, b_fc, nullptr, ub, 4096, 1024);
    // projection + residual -> output
    mma_gemm<2><<<dim3(1024 / BN, TT / BM), 256, GEMM_SMEM>>>(
        ub, wpr_t, b_pr, xa, out, 1024, 4096);
}

// round 8
// speedup vs baseline: 2.0024x; 1.6013x over previous
#include <cuda_runtime.h>
#include <math.h>
#include <stdint.h>

#define D   1024
#define T1  8192
#define T2  4096
#define TT  12288

// GEMM tiling (mma.sync tf32; R3-proven SMEM layout, 64x64 warp tiles)
#define BM 128
#define BN 128
#define BK 32
#define PAD 4
#define ROWF (BK + PAD)                          // 36 floats per SMEM row
#define STAGE_FLOATS ((BM + BN) * ROWF)          // 9216
#define STAGE_BYTES  (STAGE_FLOATS * 4)          // 36864
#define GEMM_SMEM    (2 * STAGE_BYTES)           // 73728 (double buffer)

// -------- scratch (device globals; no allocation anywhere) --------
__device__ float g_xcat[TT * D];
__device__ float g_h[TT * D];
__device__ float g_qkv[TT * 3 * D];
__device__ float g_o[TT * D];
__device__ float g_xa[TT * D];
__device__ float g_u[TT * 4 * D];
// transposed weights [N][K]
__device__ float g_wqkv_t[3 * D * D];
__device__ float g_wo_t[D * D];
__device__ float g_wfc_t[4 * D * D];
__device__ float g_wpr_t[D * 4 * D];

// ---------------- small helpers ----------------
__device__ __forceinline__ uint32_t smem_u32(const void* p) {
    uint32_t a;
    asm("{ .reg .u64 t; cvta.to.shared.u64 t, %1; cvt.u32.u64 %0, t; }"
        : "=r"(a) : "l"(p));
    return a;
}
__device__ __forceinline__ float to_tf32(float x) {
    uint32_t u;
    asm("cvt.rna.tf32.f32 %0, %1;" : "=r"(u) : "f"(x));
    return __uint_as_float(u);
}
__device__ __forceinline__ void cp16(uint32_t s, const void* g) {
    asm volatile("cp.async.cg.shared.global [%0], [%1], 16;" :: "r"(s), "l"(g));
}
__device__ __forceinline__ void cp_commit() {
    asm volatile("cp.async.commit_group;");
}
__device__ __forceinline__ void mma_tf32(float* c, uint32_t a0, uint32_t a1,
                                         uint32_t a2, uint32_t a3,
                                         uint32_t b0, uint32_t b1) {
    asm volatile(
        "mma.sync.aligned.m16n8k8.row.col.f32.tf32.tf32.f32 "
        "{%0,%1,%2,%3}, {%4,%5,%6,%7}, {%8,%9}, {%0,%1,%2,%3};"
        : "+f"(c[0]), "+f"(c[1]), "+f"(c[2]), "+f"(c[3])
        : "r"(a0), "r"(a1), "r"(a2), "r"(a3), "r"(b0), "r"(b1));
}

// ---------------- transpose (W[K][N] -> WT[N][K], tf32-rounded) ----------------
__global__ __launch_bounds__(256) void transpose_kernel(
    const float* __restrict__ in, float* __restrict__ out, int K, int N)
{
    __shared__ float t[32][33];
    int n0 = blockIdx.x * 32, k0 = blockIdx.y * 32;
    int x = threadIdx.x, y = threadIdx.y;   // 32 x 8
    #pragma unroll
    for (int i = 0; i < 32; i += 8)
        t[y + i][x] = in[(size_t)(k0 + y + i) * N + n0 + x];
    __syncthreads();
    #pragma unroll
    for (int i = 0; i < 32; i += 8)
        out[(size_t)(n0 + y + i) * K + k0 + x] = to_tf32(t[x][y + i]);
}

// ---------------- HMMA tf32 GEMM: C = A[MxK] @ BT[NxK]^T (+epilogue) ----------
// EPI: 0 = bias, 1 = bias + QuickGELU (+tf32 round), 2 = bias + residual
// 128 threads: warp grid 2(M) x 2(N), warp tile 64x64 (mt=4, nt=8).
template<int EPI>
__global__ __launch_bounds__(128, 2) void mma_gemm(
    const float* __restrict__ A, const float* __restrict__ Bt,
    const float* __restrict__ bias, const float* __restrict__ res,
    float* __restrict__ C, int N, int K)
{
    extern __shared__ float sm[];
    const int tid = threadIdx.x, wid = tid >> 5, lane = tid & 31;
    const int m0 = blockIdx.y * BM, n0 = blockIdx.x * BN;
    const int wr = wid & 1, wc = wid >> 1;          // warp grid 2 (M) x 2 (N)
    const int g = lane >> 2, tq = lane & 3;

    float c[4][8][4];
    #pragma unroll
    for (int mt = 0; mt < 4; mt++)
        #pragma unroll
        for (int nt = 0; nt < 8; nt++)
            #pragma unroll
            for (int j = 0; j < 4; j++) c[mt][nt][j] = 0.f;

    auto load_stage = [&](int s, int kb) {
        float* sA = sm + s * STAGE_FLOATS;
        float* sB = sA + BM * ROWF;
        const float* gA = A  + (size_t)m0 * K + kb * BK;
        const float* gB = Bt + (size_t)n0 * K + kb * BK;
        #pragma unroll
        for (int t = 0; t < 8; t++) {
            int ch = tid + t * 128;
            int r = ch >> 3, kc = ch & 7;
            cp16(smem_u32(sA + r * ROWF + kc * 4), gA + (size_t)r * K + kc * 4);
        }
        #pragma unroll
        for (int t = 0; t < 8; t++) {
            int ch = tid + t * 128;
            int r = ch >> 3, kc = ch & 7;
            cp16(smem_u32(sB + r * ROWF + kc * 4), gB + (size_t)r * K + kc * 4);
        }
    };

    const int iters = K / BK;
    load_stage(0, 0);
    cp_commit();

    for (int i = 0; i < iters; i++) {
        if (i + 1 < iters) {
            load_stage((i + 1) & 1, i + 1);
            cp_commit();
            asm volatile("cp.async.wait_group 1;");
        } else {
            asm volatile("cp.async.wait_group 0;");
        }
        __syncthreads();

        const float* sA = sm + (i & 1) * STAGE_FLOATS;
        const float* sB = sA + BM * ROWF;

        #pragma unroll
        for (int k0 = 0; k0 < BK; k0 += 8) {
            uint32_t a[4][4];
            #pragma unroll
            for (int mt = 0; mt < 4; mt++) {
                const float* p = sA + (wr * 64 + mt * 16 + g) * ROWF + k0 + tq;
                a[mt][0] = __float_as_uint(p[0]);
                a[mt][1] = __float_as_uint(p[8 * ROWF]);
                a[mt][2] = __float_as_uint(p[4]);
                a[mt][3] = __float_as_uint(p[8 * ROWF + 4]);
            }
            #pragma unroll
            for (int nt = 0; nt < 8; nt++) {
                const float* p = sB + (wc * 64 + nt * 8 + g) * ROWF + k0 + tq;
                uint32_t b0 = __float_as_uint(p[0]);
                uint32_t b1 = __float_as_uint(p[4]);
                #pragma unroll
                for (int mt = 0; mt < 4; mt++)
                    mma_tf32(c[mt][nt], a[mt][0], a[mt][1], a[mt][2], a[mt][3],
                             b0, b1);
            }
        }
        __syncthreads();
    }

    // epilogue: c0,c1 -> row rb, cols 2tq..2tq+1 ; c2,c3 -> row rb+8
    #pragma unroll
    for (int mt = 0; mt < 4; mt++) {
        size_t rb = (size_t)(m0 + wr * 64 + mt * 16 + g);
        #pragma unroll
        for (int nt = 0; nt < 8; nt++) {
            int col = n0 + wc * 64 + nt * 8 + tq * 2;
            float2 bi = *(const float2*)(bias + col);
            float v0 = c[mt][nt][0] + bi.x;
            float v1 = c[mt][nt][1] + bi.y;
            float v2 = c[mt][nt][2] + bi.x;
            float v3 = c[mt][nt][3] + bi.y;
            if (EPI == 1) {
                v0 = to_tf32(v0 / (1.0f + __expf(-1.702f * v0)));
                v1 = to_tf32(v1 / (1.0f + __expf(-1.702f * v1)));
                v2 = to_tf32(v2 / (1.0f + __expf(-1.702f * v2)));
                v3 = to_tf32(v3 / (1.0f + __expf(-1.702f * v3)));
            }
            if (EPI == 2) {
                float2 r0 = *(const float2*)(res + rb * N + col);
                float2 r1 = *(const float2*)(res + (rb + 8) * N + col);
                v0 += r0.x; v1 += r0.y; v2 += r1.x; v3 += r1.y;
            }
            *(float2*)(C + rb * N + col)       = make_float2(v0, v1);
            *(float2*)(C + (rb + 8) * N + col) = make_float2(v2, v3);
        }
    }
}

// ---------------- LayerNorm (tf32-rounded output) ----------------
__global__ __launch_bounds__(256) void ln_kernel(
    const float* __restrict__ x, const float* __restrict__ g,
    const float* __restrict__ b, float* __restrict__ out)
{
    int t = blockIdx.x;
    const float4* xr = (const float4*)(x + (size_t)t * D);
    float4 v = xr[threadIdx.x];
    float s  = v.x + v.y + v.z + v.w;
    float s2 = v.x*v.x + v.y*v.y + v.z*v.z + v.w*v.w;
    #pragma unroll
    for (int o = 16; o > 0; o >>= 1) {
        s  += __shfl_xor_sync(0xffffffffu, s,  o);
        s2 += __shfl_xor_sync(0xffffffffu, s2, o);
    }
    __shared__ float2 wr[8];
    __shared__ float2 stat;
    int warp = threadIdx.x >> 5, lane = threadIdx.x & 31;
    if (lane == 0) wr[warp] = make_float2(s, s2);
    __syncthreads();
    if (threadIdx.x == 0) {
        float ts = 0.f, ts2 = 0.f;
        #pragma unroll
        for (int i = 0; i < 8; i++) { ts += wr[i].x; ts2 += wr[i].y; }
        float mu  = ts * (1.0f / D);
        float var = ts2 * (1.0f / D) - mu * mu;
        stat = make_float2(mu, rsqrtf(var + 1e-5f));
    }
    __syncthreads();
    float mu = stat.x, rstd = stat.y;
    float4 gv = ((const float4*)g)[threadIdx.x];
    float4 bv = ((const float4*)b)[threadIdx.x];
    float4 o4;
    o4.x = to_tf32((v.x - mu) * rstd * gv.x + bv.x);
    o4.y = to_tf32((v.y - mu) * rstd * gv.y + bv.y);
    o4.z = to_tf32((v.z - mu) * rstd * gv.z + bv.z);
    o4.w = to_tf32((v.w - mu) * rstd * gv.w + bv.w);
    ((float4*)(out + (size_t)t * D))[threadIdx.x] = o4;
}

// ---------------- Flash attention (fp32, 64x64 tiles, DH=64) ----------------
__global__ __launch_bounds__(256) void attn_kernel(
    const float* __restrict__ qkv, float* __restrict__ o, int tok0, int N)
{
    __shared__ float Qt[64 * 64];
    __shared__ float KP[64 * 64];
    __shared__ float Vs[64 * 64];

    int tid = threadIdx.x, tx = tid & 15, ty = tid >> 4;
    int h    = blockIdx.y;
    int base = tok0 + blockIdx.z * N;
    int q0   = blockIdx.x * 64;
    int lr = tid >> 2, lp = (tid & 3) * 16;

    {
        const float* src = qkv + (size_t)(base + q0 + lr) * 3072 + h * 64 + lp;
        #pragma unroll
        for (int i = 0; i < 4; i++) {
            float4 v = *(const float4*)(src + i * 4);
            int d = lp + i * 4;
            Qt[(d + 0) * 64 + lr] = v.x * 0.125f;
            Qt[(d + 1) * 64 + lr] = v.y * 0.125f;
            Qt[(d + 2) * 64 + lr] = v.z * 0.125f;
            Qt[(d + 3) * 64 + lr] = v.w * 0.125f;
        }
    }

    float m[4], l[4], oa[4][4];
    #pragma unroll
    for (int i = 0; i < 4; i++) {
        m[i] = -1e30f; l[i] = 0.f;
        #pragma unroll
        for (int j = 0; j < 4; j++) oa[i][j] = 0.f;
    }

    for (int kt = 0; kt < N; kt += 64) {
        __syncthreads();
        {
            const float* ks = qkv + (size_t)(base + kt + lr) * 3072 + 1024 + h * 64 + lp;
            #pragma unroll
            for (int i = 0; i < 4; i++) {
                float4 kv = *(const float4*)(ks + i * 4);
                int d = lp + i * 4;
                KP[(d + 0) * 64 + lr] = kv.x;
                KP[(d + 1) * 64 + lr] = kv.y;
                KP[(d + 2) * 64 + lr] = kv.z;
                KP[(d + 3) * 64 + lr] = kv.w;
            }
            const float* vsp = ks + 1024;
            #pragma unroll
            for (int i = 0; i < 4; i++)
                *(float4*)&Vs[lr * 64 + lp + i * 4] = *(const float4*)(vsp + i * 4);
        }
        __syncthreads();

        float s[4][4];
        #pragma unroll
        for (int i = 0; i < 4; i++)
            #pragma unroll
            for (int j = 0; j < 4; j++) s[i][j] = 0.f;
        #pragma unroll 8
        for (int d = 0; d < 64; d++) {
            float4 a = *(const float4*)&Qt[d * 64 + ty * 4];
            float4 b = *(const float4*)&KP[d * 64 + tx * 4];
            s[0][0] = fmaf(a.x, b.x, s[0][0]); s[0][1] = fmaf(a.x, b.y, s[0][1]);
            s[0][2] = fmaf(a.x, b.z, s[0][2]); s[0][3] = fmaf(a.x, b.w, s[0][3]);
            s[1][0] = fmaf(a.y, b.x, s[1][0]); s[1][1] = fmaf(a.y, b.y, s[1][1]);
            s[1][2] = fmaf(a.y, b.z, s[1][2]); s[1][3] = fmaf(a.y, b.w, s[1][3]);
            s[2][0] = fmaf(a.z, b.x, s[2][0]); s[2][1] = fmaf(a.z, b.y, s[2][1]);
            s[2][2] = fmaf(a.z, b.z, s[2][2]); s[2][3] = fmaf(a.z, b.w, s[2][3]);
            s[3][0] = fmaf(a.w, b.x, s[3][0]); s[3][1] = fmaf(a.w, b.y, s[3][1]);
            s[3][2] = fmaf(a.w, b.z, s[3][2]); s[3][3] = fmaf(a.w, b.w, s[3][3]);
        }

        #pragma unroll
        for (int i = 0; i < 4; i++) {
            float tmax = fmaxf(fmaxf(s[i][0], s[i][1]), fmaxf(s[i][2], s[i][3]));
            #pragma unroll
            for (int off = 8; off > 0; off >>= 1)
                tmax = fmaxf(tmax, __shfl_xor_sync(0xffffffffu, tmax, off));
            float mn = fmaxf(m[i], tmax);
            float al = __expf(m[i] - mn);
            m[i] = mn;
            float rs = 0.f;
            #pragma unroll
            for (int j = 0; j < 4; j++) { s[i][j] = __expf(s[i][j] - mn); rs += s[i][j]; }
            #pragma unroll
            for (int off = 8; off > 0; off >>= 1)
                rs += __shfl_xor_sync(0xffffffffu, rs, off);
            l[i] = l[i] * al + rs;
            #pragma unroll
            for (int j = 0; j < 4; j++) oa[i][j] *= al;
        }

        __syncthreads();
        #pragma unroll
        for (int i = 0; i < 4; i++)
            *(float4*)&KP[(ty * 4 + i) * 64 + tx * 4] =
                make_float4(s[i][0], s[i][1], s[i][2], s[i][3]);
        __syncthreads();

        #pragma unroll 4
        for (int k = 0; k < 64; k++) {
            float4 v = *(const float4*)&Vs[k * 64 + tx * 4];
            #pragma unroll
            for (int i = 0; i < 4; i++) {
                float p = KP[(ty * 4 + i) * 64 + k];
                oa[i][0] = fmaf(p, v.x, oa[i][0]);
                oa[i][1] = fmaf(p, v.y, oa[i][1]);
                oa[i][2] = fmaf(p, v.z, oa[i][2]);
                oa[i][3] = fmaf(p, v.w, oa[i][3]);
            }
        }
    }

    #pragma unroll
    for (int i = 0; i < 4; i++) {
        float inv = 1.0f / l[i];
        int row = base + q0 + ty * 4 + i;
        float4 v = make_float4(to_tf32(oa[i][0] * inv), to_tf32(oa[i][1] * inv),
                               to_tf32(oa[i][2] * inv), to_tf32(oa[i][3] * inv));
        *(float4*)(o + (size_t)row * 1024 + h * 64 + tx * 4) = v;
    }
}

// ---------------- launch ----------------
extern "C" void kernel_launch(void* const* d_in, const int* in_sizes, int n_in,
                              void* d_out, int out_size)
{
    const float* x1    = (const float*)d_in[0];
    const float* x2    = (const float*)d_in[1];
    const float* w_qkv = (const float*)d_in[2];
    const float* b_qkv = (const float*)d_in[3];
    const float* w_o   = (const float*)d_in[4];
    const float* b_o   = (const float*)d_in[5];
    const float* g1    = (const float*)d_in[6];
    const float* be1   = (const float*)d_in[7];
    const float* w_fc  = (const float*)d_in[8];
    const float* b_fc  = (const float*)d_in[9];
    const float* w_pr  = (const float*)d_in[10];
    const float* b_pr  = (const float*)d_in[11];
    const float* g2    = (const float*)d_in[12];
    const float* be2   = (const float*)d_in[13];
    float* out = (float*)d_out;

    float *xcat, *h, *qkvb, *ob, *xa, *ub;
    float *wqkv_t, *wo_t, *wfc_t, *wpr_t;
    cudaGetSymbolAddress((void**)&xcat,   g_xcat);
    cudaGetSymbolAddress((void**)&h,      g_h);
    cudaGetSymbolAddress((void**)&qkvb,   g_qkv);
    cudaGetSymbolAddress((void**)&ob,     g_o);
    cudaGetSymbolAddress((void**)&xa,     g_xa);
    cudaGetSymbolAddress((void**)&ub,     g_u);
    cudaGetSymbolAddress((void**)&wqkv_t, g_wqkv_t);
    cudaGetSymbolAddress((void**)&wo_t,   g_wo_t);
    cudaGetSymbolAddress((void**)&wfc_t,  g_wfc_t);
    cudaGetSymbolAddress((void**)&wpr_t,  g_wpr_t);

    cudaFuncSetAttribute(mma_gemm<0>, cudaFuncAttributeMaxDynamicSharedMemorySize, GEMM_SMEM);
    cudaFuncSetAttribute(mma_gemm<1>, cudaFuncAttributeMaxDynamicSharedMemorySize, GEMM_SMEM);
    cudaFuncSetAttribute(mma_gemm<2>, cudaFuncAttributeMaxDynamicSharedMemorySize, GEMM_SMEM);

    // concat tokens
    cudaMemcpyAsync(xcat, x1, (size_t)T1 * D * sizeof(float),
                    cudaMemcpyDeviceToDevice, 0);
    cudaMemcpyAsync(xcat + (size_t)T1 * D, x2, (size_t)T2 * D * sizeof(float),
                    cudaMemcpyDeviceToDevice, 0);

    // weight transposes (tf32-rounded)
    transpose_kernel<<<dim3(3072 / 32, 1024 / 32), dim3(32, 8)>>>(w_qkv, wqkv_t, 1024, 3072);
    transpose_kernel<<<dim3(1024 / 32, 1024 / 32), dim3(32, 8)>>>(w_o,   wo_t,   1024, 1024);
    transpose_kernel<<<dim3(4096 / 32, 1024 / 32), dim3(32, 8)>>>(w_fc,  wfc_t,  1024, 4096);
    transpose_kernel<<<dim3(1024 / 32, 4096 / 32), dim3(32, 8)>>>(w_pr,  wpr_t,  4096, 1024);

    // LN1
    ln_kernel<<<TT, 256>>>(xcat, g1, be1, h);
    // QKV projection
    mma_gemm<0><<<dim3(3072 / BN, TT / BM), 128, GEMM_SMEM>>>(
        h, wqkv_t, b_qkv, nullptr, qkvb, 3072, 1024);
    // attention
    attn_kernel<<<dim3(16, 16, 8),  256>>>(qkvb, ob, 0,  1024);
    attn_kernel<<<dim3(4,  16, 16), 256>>>(qkvb, ob, T1, 256);
    // out projection + residual
    mma_gemm<2><<<dim3(1024 / BN, TT / BM), 128, GEMM_SMEM>>>(
        ob, wo_t, b_o, xcat, xa, 1024, 1024);
    // LN2
    ln_kernel<<<TT, 256>>>(xa, g2, be2, h);
    // FC + QuickGELU
    mma_gemm<1><<<dim3(4096 / BN, TT / BM), 128, GEMM_SMEM>>>(
        h, wfc_t, b_fc, nullptr, ub, 4096, 1024);
    // projection + residual -> output
    mma_gemm<2><<<dim3(1024 / BN, TT / BM), 128, GEMM_SMEM>>>(
        ub, wpr_t, b_pr, xa, out, 1024, 4096);
}

// round 12
// speedup vs baseline: 2.8821x; 1.4393x over previous
#include <cuda_runtime.h>
#include <cuda_fp16.h>
#include <math.h>
#include <stdint.h>

#define D   1024
#define T1  8192
#define T2  4096
#define TT  12288

// GEMM tiling (mma.sync fp16 m16n8k16, ldmatrix fragment loads)
#define BM 128
#define BN 128
#define BK 32
#define ROWH 40                                   // halves per SMEM row (80 B)
#define STAGE_HALVES ((BM + BN) * ROWH)           // 10240 halves
#define STAGE_BYTES  (STAGE_HALVES * 2)           // 20480
#define GEMM_SMEM    (2 * STAGE_BYTES)            // 40960 (double buffer, 2 CTA/SM)

// -------- scratch (device globals; no allocation anywhere) --------
__device__ __align__(256) float  g_xcat[TT * D];
__device__ __align__(256) __half g_h[TT * D];          // LN output (fp16)
__device__ __align__(256) float  g_qkv[TT * 3 * D];    // qkv (fp32, attention input)
__device__ __align__(256) __half g_o[TT * D];          // attention output (fp16)
__device__ __align__(256) float  g_xa[TT * D];
__device__ __align__(256) __half g_u[TT * 4 * D];      // MLP hidden (fp16)
// transposed weights [N][K] fp16
__device__ __align__(256) __half g_wqkv_t[3 * D * D];
__device__ __align__(256) __half g_wo_t[D * D];
__device__ __align__(256) __half g_wfc_t[4 * D * D];
__device__ __align__(256) __half g_wpr_t[D * 4 * D];

// ---------------- small helpers ----------------
__device__ __forceinline__ uint32_t smem_u32(const void* p) {
    uint32_t a;
    asm("{ .reg .u64 t; cvta.to.shared.u64 t, %1; cvt.u32.u64 %0, t; }"
        : "=r"(a) : "l"(p));
    return a;
}
__device__ __forceinline__ uint32_t h2_as_u32(__half2 h) {
    uint32_t u;
    memcpy(&u, &h, 4);
    return u;
}
__device__ __forceinline__ void cp16(uint32_t s, const void* g) {
    asm volatile("cp.async.cg.shared.global [%0], [%1], 16;" :: "r"(s), "l"(g));
}
__device__ __forceinline__ void cp_commit() {
    asm volatile("cp.async.commit_group;");
}
__device__ __forceinline__ void ldm_x4(uint32_t* r, uint32_t addr) {
    asm volatile("ldmatrix.sync.aligned.m8n8.x4.shared.b16 {%0,%1,%2,%3}, [%4];"
                 : "=r"(r[0]), "=r"(r[1]), "=r"(r[2]), "=r"(r[3]) : "r"(addr));
}
__device__ __forceinline__ void mma_f16(float* c, const uint32_t* a,
                                        uint32_t b0, uint32_t b1) {
    asm volatile(
        "mma.sync.aligned.m16n8k16.row.col.f32.f16.f16.f32 "
        "{%0,%1,%2,%3}, {%4,%5,%6,%7}, {%8,%9}, {%0,%1,%2,%3};"
        : "+f"(c[0]), "+f"(c[1]), "+f"(c[2]), "+f"(c[3])
        : "r"(a[0]), "r"(a[1]), "r"(a[2]), "r"(a[3]), "r"(b0), "r"(b1));
}

// ---------------- transpose (W[K][N] fp32 -> WT[N][K] fp16) ----------------
__global__ __launch_bounds__(256) void transpose_kernel(
    const float* __restrict__ in, __half* __restrict__ out, int K, int N)
{
    __shared__ float t[32][33];
    int n0 = blockIdx.x * 32, k0 = blockIdx.y * 32;
    int x = threadIdx.x, y = threadIdx.y;   // 32 x 8
    #pragma unroll
    for (int i = 0; i < 32; i += 8)
        t[y + i][x] = in[(size_t)(k0 + y + i) * N + n0 + x];
    __syncthreads();
    #pragma unroll
    for (int i = 0; i < 32; i += 8)
        out[(size_t)(n0 + y + i) * K + k0 + x] = __float2half_rn(t[x][y + i]);
}

// ---------------- fp16 MMA GEMM: C = A[MxK] @ BT[NxK]^T (+epilogue) ----------
// EPI: 0 = bias, 1 = bias + QuickGELU, 2 = bias + residual(fp32)
// OT: float or __half output
// 128 threads: warp grid 2(M) x 2(N), warp tile 64x64 (mt=4, nt=8).
template<int EPI, typename OT>
__global__ __launch_bounds__(128, 2) void mma_gemm(
    const __half* __restrict__ A, const __half* __restrict__ Bt,
    const float* __restrict__ bias, const float* __restrict__ res,
    OT* __restrict__ C, int N, int K)
{
    extern __shared__ __half smh[];
    const int tid = threadIdx.x, wid = tid >> 5, lane = tid & 31;
    const int m0 = blockIdx.y * BM, n0 = blockIdx.x * BN;
    const int wr = wid & 1, wc = wid >> 1;
    const int g = lane >> 2, tq = lane & 3;

    float c[4][8][4];
    #pragma unroll
    for (int mt = 0; mt < 4; mt++)
        #pragma unroll
        for (int nt = 0; nt < 8; nt++)
            #pragma unroll
            for (int j = 0; j < 4; j++) c[mt][nt][j] = 0.f;

    // stage loader: A 128x32h (64B/row, 4 chunks) + B 128x32h
    auto load_stage = [&](int s, int kb) {
        __half* sA = smh + s * STAGE_HALVES;
        __half* sB = sA + BM * ROWH;
        const __half* gA = A  + (size_t)m0 * K + kb * BK;
        const __half* gB = Bt + (size_t)n0 * K + kb * BK;
        #pragma unroll
        for (int t = 0; t < 4; t++) {
            int ch = tid + t * 128;
            int r = ch >> 2, kc = ch & 3;
            cp16(smem_u32(sA + r * ROWH + kc * 8), gA + (size_t)r * K + kc * 8);
        }
        #pragma unroll
        for (int t = 0; t < 4; t++) {
            int ch = tid + t * 128;
            int r = ch >> 2, kc = ch & 3;
            cp16(smem_u32(sB + r * ROWH + kc * 8), gB + (size_t)r * K + kc * 8);
        }
    };

    const int iters = K / BK;
    load_stage(0, 0);
    cp_commit();

    // ldmatrix lane->row/col mapping
    const int a_row = (lane & 15);          // + mt*16 + wr*64
    const int a_coff = ((lane >> 4) & 1) * 8;
    const int b_row = (lane & 7) + (((lane >> 4) & 1) * 8);  // + p*16 + wc*64
    const int b_coff = ((lane >> 3) & 1) * 8;

    for (int i = 0; i < iters; i++) {
        if (i + 1 < iters) {
            load_stage((i + 1) & 1, i + 1);
            cp_commit();
            asm volatile("cp.async.wait_group 1;");
        } else {
            asm volatile("cp.async.wait_group 0;");
        }
        __syncthreads();

        const __half* sA = smh + (i & 1) * STAGE_HALVES;
        const __half* sB = sA + BM * ROWH;
        const uint32_t sAu = smem_u32(sA), sBu = smem_u32(sB);

        #pragma unroll
        for (int kk = 0; kk < 2; kk++) {
            const int k0 = kk * 16;
            uint32_t a[4][4];
            #pragma unroll
            for (int mt = 0; mt < 4; mt++)
                ldm_x4(a[mt], sAu + 2 * ((wr * 64 + mt * 16 + a_row) * ROWH
                                         + k0 + a_coff));
            #pragma unroll
            for (int p = 0; p < 4; p++) {
                uint32_t b[4];
                ldm_x4(b, sBu + 2 * ((wc * 64 + p * 16 + b_row) * ROWH
                                     + k0 + b_coff));
                #pragma unroll
                for (int mt = 0; mt < 4; mt++) {
                    mma_f16(c[mt][2 * p + 0], a[mt], b[0], b[1]);
                    mma_f16(c[mt][2 * p + 1], a[mt], b[2], b[3]);
                }
            }
        }
        __syncthreads();
    }

    // epilogue: c0,c1 -> row rb, cols 2tq..2tq+1 ; c2,c3 -> row rb+8
    #pragma unroll
    for (int mt = 0; mt < 4; mt++) {
        size_t rb = (size_t)(m0 + wr * 64 + mt * 16 + g);
        #pragma unroll
        for (int nt = 0; nt < 8; nt++) {
            int col = n0 + wc * 64 + nt * 8 + tq * 2;
            float2 bi = *(const float2*)(bias + col);
            float v0 = c[mt][nt][0] + bi.x;
            float v1 = c[mt][nt][1] + bi.y;
            float v2 = c[mt][nt][2] + bi.x;
            float v3 = c[mt][nt][3] + bi.y;
            if (EPI == 1) {
                v0 = v0 / (1.0f + __expf(-1.702f * v0));
                v1 = v1 / (1.0f + __expf(-1.702f * v1));
                v2 = v2 / (1.0f + __expf(-1.702f * v2));
                v3 = v3 / (1.0f + __expf(-1.702f * v3));
            }
            if (EPI == 2) {
                float2 r0 = *(const float2*)(res + rb * N + col);
                float2 r1 = *(const float2*)(res + (rb + 8) * N + col);
                v0 += r0.x; v1 += r0.y; v2 += r1.x; v3 += r1.y;
            }
            if (sizeof(OT) == 4) {
                *(float2*)((float*)C + rb * N + col)       = make_float2(v0, v1);
                *(float2*)((float*)C + (rb + 8) * N + col) = make_float2(v2, v3);
            } else {
                *(uint32_t*)((__half*)C + rb * N + col) =
                    h2_as_u32(__floats2half2_rn(v0, v1));
                *(uint32_t*)((__half*)C + (rb + 8) * N + col) =
                    h2_as_u32(__floats2half2_rn(v2, v3));
            }
        }
    }
}

// ---------------- LayerNorm (fp32 in -> fp16 out) ----------------
__global__ __launch_bounds__(256) void ln_kernel(
    const float* __restrict__ x, const float* __restrict__ g,
    const float* __restrict__ b, __half* __restrict__ out)
{
    int t = blockIdx.x;
    const float4* xr = (const float4*)(x + (size_t)t * D);
    float4 v = xr[threadIdx.x];
    float s  = v.x + v.y + v.z + v.w;
    float s2 = v.x*v.x + v.y*v.y + v.z*v.z + v.w*v.w;
    #pragma unroll
    for (int o = 16; o > 0; o >>= 1) {
        s  += __shfl_xor_sync(0xffffffffu, s,  o);
        s2 += __shfl_xor_sync(0xffffffffu, s2, o);
    }
    __shared__ float2 wr[8];
    __shared__ float2 stat;
    int warp = threadIdx.x >> 5, lane = threadIdx.x & 31;
    if (lane == 0) wr[warp] = make_float2(s, s2);
    __syncthreads();
    if (threadIdx.x == 0) {
        float ts = 0.f, ts2 = 0.f;
        #pragma unroll
        for (int i = 0; i < 8; i++) { ts += wr[i].x; ts2 += wr[i].y; }
        float mu  = ts * (1.0f / D);
        float var = ts2 * (1.0f / D) - mu * mu;
        stat = make_float2(mu, rsqrtf(var + 1e-5f));
    }
    __syncthreads();
    float mu = stat.x, rstd = stat.y;
    float4 gv = ((const float4*)g)[threadIdx.x];
    float4 bv = ((const float4*)b)[threadIdx.x];
    uint2 u;
    u.x = h2_as_u32(__floats2half2_rn((v.x - mu) * rstd * gv.x + bv.x,
                                      (v.y - mu) * rstd * gv.y + bv.y));
    u.y = h2_as_u32(__floats2half2_rn((v.z - mu) * rstd * gv.z + bv.z,
                                      (v.w - mu) * rstd * gv.w + bv.w));
    ((uint2*)(out + (size_t)t * D))[threadIdx.x] = u;
}

// ---------------- Flash attention (fp32 in, fp16 out, 64x64 tiles) ----------------
__global__ __launch_bounds__(256) void attn_kernel(
    const float* __restrict__ qkv, __half* __restrict__ o, int tok0, int N)
{
    __shared__ float Qt[64 * 64];
    __shared__ float KP[64 * 64];
    __shared__ float Vs[64 * 64];

    int tid = threadIdx.x, tx = tid & 15, ty = tid >> 4;
    int h    = blockIdx.y;
    int base = tok0 + blockIdx.z * N;
    int q0   = blockIdx.x * 64;
    int lr = tid >> 2, lp = (tid & 3) * 16;

    {
        const float* src = qkv + (size_t)(base + q0 + lr) * 3072 + h * 64 + lp;
        #pragma unroll
        for (int i = 0; i < 4; i++) {
            float4 v = *(const float4*)(src + i * 4);
            int d = lp + i * 4;
            Qt[(d + 0) * 64 + lr] = v.x * 0.125f;
            Qt[(d + 1) * 64 + lr] = v.y * 0.125f;
            Qt[(d + 2) * 64 + lr] = v.z * 0.125f;
            Qt[(d + 3) * 64 + lr] = v.w * 0.125f;
        }
    }

    float m[4], l[4], oa[4][4];
    #pragma unroll
    for (int i = 0; i < 4; i++) {
        m[i] = -1e30f; l[i] = 0.f;
        #pragma unroll
        for (int j = 0; j < 4; j++) oa[i][j] = 0.f;
    }

    for (int kt = 0; kt < N; kt += 64) {
        __syncthreads();
        {
            const float* ks = qkv + (size_t)(base + kt + lr) * 3072 + 1024 + h * 64 + lp;
            #pragma unroll
            for (int i = 0; i < 4; i++) {
                float4 kv = *(const float4*)(ks + i * 4);
                int d = lp + i * 4;
                KP[(d + 0) * 64 + lr] = kv.x;
                KP[(d + 1) * 64 + lr] = kv.y;
                KP[(d + 2) * 64 + lr] = kv.z;
                KP[(d + 3) * 64 + lr] = kv.w;
            }
            const float* vsp = ks + 1024;
            #pragma unroll
            for (int i = 0; i < 4; i++)
                *(float4*)&Vs[lr * 64 + lp + i * 4] = *(const float4*)(vsp + i * 4);
        }
        __syncthreads();

        float s[4][4];
        #pragma unroll
        for (int i = 0; i < 4; i++)
            #pragma unroll
            for (int j = 0; j < 4; j++) s[i][j] = 0.f;
        #pragma unroll 8
        for (int d = 0; d < 64; d++) {
            float4 a = *(const float4*)&Qt[d * 64 + ty * 4];
            float4 b = *(const float4*)&KP[d * 64 + tx * 4];
            s[0][0] = fmaf(a.x, b.x, s[0][0]); s[0][1] = fmaf(a.x, b.y, s[0][1]);
            s[0][2] = fmaf(a.x, b.z, s[0][2]); s[0][3] = fmaf(a.x, b.w, s[0][3]);
            s[1][0] = fmaf(a.y, b.x, s[1][0]); s[1][1] = fmaf(a.y, b.y, s[1][1]);
            s[1][2] = fmaf(a.y, b.z, s[1][2]); s[1][3] = fmaf(a.y, b.w, s[1][3]);
            s[2][0] = fmaf(a.z, b.x, s[2][0]); s[2][1] = fmaf(a.z, b.y, s[2][1]);
            s[2][2] = fmaf(a.z, b.z, s[2][2]); s[2][3] = fmaf(a.z, b.w, s[2][3]);
            s[3][0] = fmaf(a.w, b.x, s[3][0]); s[3][1] = fmaf(a.w, b.y, s[3][1]);
            s[3][2] = fmaf(a.w, b.z, s[3][2]); s[3][3] = fmaf(a.w, b.w, s[3][3]);
        }

        #pragma unroll
        for (int i = 0; i < 4; i++) {
            float tmax = fmaxf(fmaxf(s[i][0], s[i][1]), fmaxf(s[i][2], s[i][3]));
            #pragma unroll
            for (int off = 8; off > 0; off >>= 1)
                tmax = fmaxf(tmax, __shfl_xor_sync(0xffffffffu, tmax, off));
            float mn = fmaxf(m[i], tmax);
            float al = __expf(m[i] - mn);
            m[i] = mn;
            float rs = 0.f;
            #pragma unroll
            for (int j = 0; j < 4; j++) { s[i][j] = __expf(s[i][j] - mn); rs += s[i][j]; }
            #pragma unroll
            for (int off = 8; off > 0; off >>= 1)
                rs += __shfl_xor_sync(0xffffffffu, rs, off);
            l[i] = l[i] * al + rs;
            #pragma unroll
            for (int j = 0; j < 4; j++) oa[i][j] *= al;
        }

        __syncthreads();
        #pragma unroll
        for (int i = 0; i < 4; i++)
            *(float4*)&KP[(ty * 4 + i) * 64 + tx * 4] =
                make_float4(s[i][0], s[i][1], s[i][2], s[i][3]);
        __syncthreads();

        #pragma unroll 4
        for (int k = 0; k < 64; k++) {
            float4 v = *(const float4*)&Vs[k * 64 + tx * 4];
            #pragma unroll
            for (int i = 0; i < 4; i++) {
                float p = KP[(ty * 4 + i) * 64 + k];
                oa[i][0] = fmaf(p, v.x, oa[i][0]);
                oa[i][1] = fmaf(p, v.y, oa[i][1]);
                oa[i][2] = fmaf(p, v.z, oa[i][2]);
                oa[i][3] = fmaf(p, v.w, oa[i][3]);
            }
        }
    }

    #pragma unroll
    for (int i = 0; i < 4; i++) {
        float inv = 1.0f / l[i];
        int row = base + q0 + ty * 4 + i;
        uint2 st;
        st.x = h2_as_u32(__floats2half2_rn(oa[i][0] * inv, oa[i][1] * inv));
        st.y = h2_as_u32(__floats2half2_rn(oa[i][2] * inv, oa[i][3] * inv));
        *(uint2*)(o + (size_t)row * 1024 + h * 64 + tx * 4) = st;
    }
}

// ---------------- launch ----------------
extern "C" void kernel_launch(void* const* d_in, const int* in_sizes, int n_in,
                              void* d_out, int out_size)
{
    const float* x1    = (const float*)d_in[0];
    const float* x2    = (const float*)d_in[1];
    const float* w_qkv = (const float*)d_in[2];
    const float* b_qkv = (const float*)d_in[3];
    const float* w_o   = (const float*)d_in[4];
    const float* b_o   = (const float*)d_in[5];
    const float* g1    = (const float*)d_in[6];
    const float* be1   = (const float*)d_in[7];
    const float* w_fc  = (const float*)d_in[8];
    const float* b_fc  = (const float*)d_in[9];
    const float* w_pr  = (const float*)d_in[10];
    const float* b_pr  = (const float*)d_in[11];
    const float* g2    = (const float*)d_in[12];
    const float* be2   = (const float*)d_in[13];
    float* out = (float*)d_out;

    float *xcat, *qkvb, *xa;
    __half *h, *ob, *ub, *wqkv_t, *wo_t, *wfc_t, *wpr_t;
    cudaGetSymbolAddress((void**)&xcat,   g_xcat);
    cudaGetSymbolAddress((void**)&h,      g_h);
    cudaGetSymbolAddress((void**)&qkvb,   g_qkv);
    cudaGetSymbolAddress((void**)&ob,     g_o);
    cudaGetSymbolAddress((void**)&xa,     g_xa);
    cudaGetSymbolAddress((void**)&ub,     g_u);
    cudaGetSymbolAddress((void**)&wqkv_t, g_wqkv_t);
    cudaGetSymbolAddress((void**)&wo_t,   g_wo_t);
    cudaGetSymbolAddress((void**)&wfc_t,  g_wfc_t);
    cudaGetSymbolAddress((void**)&wpr_t,  g_wpr_t);

    cudaFuncSetAttribute((const void*)mma_gemm<0, float>,
                         cudaFuncAttributeMaxDynamicSharedMemorySize, GEMM_SMEM);
    cudaFuncSetAttribute((const void*)mma_gemm<1, __half>,
                         cudaFuncAttributeMaxDynamicSharedMemorySize, GEMM_SMEM);
    cudaFuncSetAttribute((const void*)mma_gemm<2, float>,
                         cudaFuncAttributeMaxDynamicSharedMemorySize, GEMM_SMEM);

    // concat tokens
    cudaMemcpyAsync(xcat, x1, (size_t)T1 * D * sizeof(float),
                    cudaMemcpyDeviceToDevice, 0);
    cudaMemcpyAsync(xcat + (size_t)T1 * D, x2, (size_t)T2 * D * sizeof(float),
                    cudaMemcpyDeviceToDevice, 0);

    // weight transposes (fp32 -> fp16)
    transpose_kernel<<<dim3(3072 / 32, 1024 / 32), dim3(32, 8)>>>(w_qkv, wqkv_t, 1024, 3072);
    transpose_kernel<<<dim3(1024 / 32, 1024 / 32), dim3(32, 8)>>>(w_o,   wo_t,   1024, 1024);
    transpose_kernel<<<dim3(4096 / 32, 1024 / 32), dim3(32, 8)>>>(w_fc,  wfc_t,  1024, 4096);
    transpose_kernel<<<dim3(1024 / 32, 4096 / 32), dim3(32, 8)>>>(w_pr,  wpr_t,  4096, 1024);

    // LN1
    ln_kernel<<<TT, 256>>>(xcat, g1, be1, h);
    // QKV projection (fp16 in, fp32 out)
    mma_gemm<0, float><<<dim3(3072 / BN, TT / BM), 128, GEMM_SMEM>>>(
        h, wqkv_t, b_qkv, nullptr, qkvb, 3072, 1024);
    // attention (fp32 in, fp16 out)
    attn_kernel<<<dim3(16, 16, 8),  256>>>(qkvb, ob, 0,  1024);
    attn_kernel<<<dim3(4,  16, 16), 256>>>(qkvb, ob, T1, 256);
    // out projection + residual (fp32 out)
    mma_gemm<2, float><<<dim3(1024 / BN, TT / BM), 128, GEMM_SMEM>>>(
        ob, wo_t, b_o, xcat, xa, 1024, 1024);
    // LN2
    ln_kernel<<<TT, 256>>>(xa, g2, be2, h);
    // FC + QuickGELU (fp16 out -> next GEMM input)
    mma_gemm<1, __half><<<dim3(4096 / BN, TT / BM), 128, GEMM_SMEM>>>(
        h, wfc_t, b_fc, nullptr, ub, 4096, 1024);
    // projection + residual -> output (fp32)
    mma_gemm<2, float><<<dim3(1024 / BN, TT / BM), 128, GEMM_SMEM>>>(
        ub, wpr_t, b_pr, xa, out, 1024, 4096);
}